// round 1
// baseline (speedup 1.0000x reference)
#include <cuda_runtime.h>
#include <cstdint>
#include <cstddef>

#define B_TOTAL 65536
#define NGRAPH  64
#define NNODES  2048
#define NEDGES  16384
#define META    64
#define TXD     8
#define NOISE   128
#define RROWS   32   // rows per block in main kernel (16 row-pairs)

typedef unsigned long long ull;

// Scratch: per-graph output contribution incl. emb_b folded in. [64][128]
__device__ float g_go[NGRAPH * NOISE];

// ---------- f32x2 helpers (Blackwell packed fp32 FMA; ptxas never auto-fuses) ----------
__device__ __forceinline__ ull pack2(float lo, float hi) {
    ull r; asm("mov.b64 %0, {%1,%2};" : "=l"(r) : "f"(lo), "f"(hi)); return r;
}
__device__ __forceinline__ ull fma2(ull a, ull b, ull c) {
    ull d; asm("fma.rn.f32x2 %0, %1, %2, %3;" : "=l"(d) : "l"(a), "l"(b), "l"(c)); return d;
}
__device__ __forceinline__ void unpack2(ull v, float& lo, float& hi) {
    asm("mov.b64 {%0,%1}, %2;" : "=f"(lo), "=f"(hi) : "l"(v));
}

// ============================================================================
// Kernel 1: per-graph GCN embedding + fold through emb_W[:2048,:] into g_go.
// One block per graph. deg/agg in shared via atomics, then a 2048x128 GEMM
// (16 K-slices x 32 col-quads of float4) with a shared-memory reduction.
// g_go[g][j] = sum_n (agg[n]*w + b) * emb_W[n][j] + emb_b[j]
// ============================================================================
__global__ __launch_bounds__(512) void gcn_precompute(
    const int* __restrict__ edges, const float* __restrict__ gwp,
    const float* __restrict__ gbp, const float* __restrict__ embW,
    const float* __restrict__ embb)
{
    __shared__ float deg[NNODES];                 // then reused as dinv
    __shared__ float agg[NNODES];
    __shared__ __align__(16) float red[16 * 32 * 4];

    const int g   = blockIdx.x;
    const int tid = threadIdx.x;
    const int* src = edges + (size_t)g * 2 * NEDGES;
    const int* dst = src + NEDGES;

    // deg init = 1 (self loop)
    for (int n = tid; n < NNODES; n += 512) deg[n] = 1.0f;
    __syncthreads();
    for (int e = tid; e < NEDGES; e += 512) atomicAdd(&deg[dst[e]], 1.0f);
    __syncthreads();
    // dinv + self-loop term dinv^2
    for (int n = tid; n < NNODES; n += 512) {
        float dv = rsqrtf(deg[n]);
        deg[n] = dv;
        agg[n] = dv * dv;
    }
    __syncthreads();
    for (int e = tid; e < NEDGES; e += 512) {
        int s = src[e], d = dst[e];
        atomicAdd(&agg[d], deg[s] * deg[d]);
    }
    __syncthreads();
    const float w = gwp[0], b = gbp[0];
    for (int n = tid; n < NNODES; n += 512) agg[n] = fmaf(agg[n], w, b);
    __syncthreads();

    // GEMM: thread (slice s=tid>>5 over K, colquad c=tid&31 over N)
    const int c = tid & 31;
    const int s = tid >> 5;
    const float4* W4 = reinterpret_cast<const float4*>(embW);  // row n -> W4[n*32 + c]
    float4 acc = make_float4(0.f, 0.f, 0.f, 0.f);
    #pragma unroll 4
    for (int n = s * 128; n < s * 128 + 128; n++) {
        float a = agg[n];
        float4 wv = __ldg(&W4[(size_t)n * 32 + c]);
        acc.x = fmaf(a, wv.x, acc.x);
        acc.y = fmaf(a, wv.y, acc.y);
        acc.z = fmaf(a, wv.z, acc.z);
        acc.w = fmaf(a, wv.w, acc.w);
    }
    reinterpret_cast<float4*>(red)[s * 32 + c] = acc;
    __syncthreads();
    if (tid < NOISE) {
        float sum = embb[tid];
        int cg = tid >> 2, comp = tid & 3;
        #pragma unroll
        for (int s2 = 0; s2 < 16; s2++)
            sum += red[(s2 * 32 + cg) * 4 + comp];
        g_go[g * NOISE + tid] = sum;
    }
}

// ============================================================================
// Kernel 2: fused trig-MLP + output GEMM, f32x2 over row pairs.
// Block = 128 threads, RROWS=32 rows. Shared staging is transposed
// [feature][row] with +2 padding so row-pairs are one aligned 8B LDS.
// Phase 1: trig[32][R] = relu(td @ trig_W + trig_b)   (4 row-pairs / thread)
// Phase 2: thread = (col jj & jj+64, 8 row-pairs); per k: 1 LDS.64 -> 2 FFMA2.
// ============================================================================
__global__ __launch_bounds__(128) void noise_main(
    const int*   __restrict__ gid,   const float* __restrict__ chain,
    const float* __restrict__ td,    const float* __restrict__ tx,
    const float* __restrict__ trigW, const float* __restrict__ trigb,
    const float* __restrict__ embW,  float* __restrict__ out)
{
    __shared__ __align__(16) float td_s[META][RROWS + 2];
    __shared__ __align__(16) float trig_s[32][RROWS + 2];
    __shared__ __align__(16) float tx_s[TXD][RROWS + 2];
    __shared__ float ch_s[RROWS];
    __shared__ int   gs[RROWS];
    __shared__ __align__(16) float tw_s[META * 32];

    const int tid = threadIdx.x;
    const int r0  = blockIdx.x * RROWS;

    // ---- stage inputs (transposed) ----
    {
        const float4* tdg = reinterpret_cast<const float4*>(td + (size_t)r0 * META);
        for (int i = tid; i < RROWS * (META / 4); i += 128) {
            float4 v = tdg[i];
            int r = i / (META / 4);
            int m = (i % (META / 4)) * 4;
            td_s[m + 0][r] = v.x; td_s[m + 1][r] = v.y;
            td_s[m + 2][r] = v.z; td_s[m + 3][r] = v.w;
        }
        const float4* txg = reinterpret_cast<const float4*>(tx + (size_t)r0 * TXD);
        for (int i = tid; i < RROWS * (TXD / 4); i += 128) {
            float4 v = txg[i];
            int r = i / (TXD / 4);
            int m = (i % (TXD / 4)) * 4;
            tx_s[m + 0][r] = v.x; tx_s[m + 1][r] = v.y;
            tx_s[m + 2][r] = v.z; tx_s[m + 3][r] = v.w;
        }
        const float4* twg = reinterpret_cast<const float4*>(trigW);
        for (int i = tid; i < META * 32 / 4; i += 128)
            reinterpret_cast<float4*>(tw_s)[i] = twg[i];
        if (tid < RROWS) { ch_s[tid] = chain[r0 + tid]; gs[tid] = gid[r0 + tid]; }
    }
    __syncthreads();

    // ---- phase 1: trig projection + relu (row-paired) ----
    {
        const int k = tid & 31;   // output feature
        const int w = tid >> 5;   // warp -> pairs {w, w+4, w+8, w+12}
        float tb = __ldg(&trigb[k]);
        ull acc0 = pack2(tb, tb), acc1 = acc0, acc2 = acc0, acc3 = acc0;
        #pragma unroll 16
        for (int m = 0; m < META; m++) {
            float wv = tw_s[m * 32 + k];
            ull wd = pack2(wv, wv);
            ull t0 = *reinterpret_cast<const ull*>(&td_s[m][2 * (w)]);
            ull t1 = *reinterpret_cast<const ull*>(&td_s[m][2 * (w + 4)]);
            ull t2 = *reinterpret_cast<const ull*>(&td_s[m][2 * (w + 8)]);
            ull t3 = *reinterpret_cast<const ull*>(&td_s[m][2 * (w + 12)]);
            acc0 = fma2(wd, t0, acc0);
            acc1 = fma2(wd, t1, acc1);
            acc2 = fma2(wd, t2, acc2);
            acc3 = fma2(wd, t3, acc3);
        }
        float a, b2;
        unpack2(acc0, a, b2);
        *reinterpret_cast<ull*>(&trig_s[k][2 * (w)])      = pack2(fmaxf(a, 0.f), fmaxf(b2, 0.f));
        unpack2(acc1, a, b2);
        *reinterpret_cast<ull*>(&trig_s[k][2 * (w + 4)])  = pack2(fmaxf(a, 0.f), fmaxf(b2, 0.f));
        unpack2(acc2, a, b2);
        *reinterpret_cast<ull*>(&trig_s[k][2 * (w + 8)])  = pack2(fmaxf(a, 0.f), fmaxf(b2, 0.f));
        unpack2(acc3, a, b2);
        *reinterpret_cast<ull*>(&trig_s[k][2 * (w + 12)]) = pack2(fmaxf(a, 0.f), fmaxf(b2, 0.f));
    }
    __syncthreads();

    // ---- phase 2: output GEMM ----
    {
        const int jj    = tid & 63;   // this thread: columns jj and jj+64
        const int half  = tid >> 6;
        const int pbase = half * 8;   // 8 row-pairs
        ull accA[8], accB[8];

        const float wch0 = __ldg(&embW[2048 * NOISE + jj]);
        const float wch1 = __ldg(&embW[2048 * NOISE + jj + 64]);
        #pragma unroll
        for (int pi = 0; pi < 8; pi++) {
            int p  = pbase + pi;
            int ra = 2 * p, rb = 2 * p + 1;
            int ga = gs[ra], gb = gs[rb];
            float ca = ch_s[ra], cb = ch_s[rb];
            float a0 = __ldg(&g_go[ga * NOISE + jj]);
            float b0 = __ldg(&g_go[gb * NOISE + jj]);
            float a1 = __ldg(&g_go[ga * NOISE + jj + 64]);
            float b1 = __ldg(&g_go[gb * NOISE + jj + 64]);
            accA[pi] = pack2(fmaf(ca, wch0, a0), fmaf(cb, wch0, b0));
            accB[pi] = pack2(fmaf(ca, wch1, a1), fmaf(cb, wch1, b1));
        }
        #pragma unroll 8
        for (int k = 0; k < 32; k++) {
            float w0 = __ldg(&embW[(2049 + k) * NOISE + jj]);
            float w1 = __ldg(&embW[(2049 + k) * NOISE + jj + 64]);
            ull wd0 = pack2(w0, w0), wd1 = pack2(w1, w1);
            #pragma unroll
            for (int pi = 0; pi < 8; pi++) {
                ull t2 = *reinterpret_cast<const ull*>(&trig_s[k][2 * (pbase + pi)]);
                accA[pi] = fma2(wd0, t2, accA[pi]);
                accB[pi] = fma2(wd1, t2, accB[pi]);
            }
        }
        #pragma unroll
        for (int i = 0; i < TXD; i++) {
            float w0 = __ldg(&embW[(2081 + i) * NOISE + jj]);
            float w1 = __ldg(&embW[(2081 + i) * NOISE + jj + 64]);
            ull wd0 = pack2(w0, w0), wd1 = pack2(w1, w1);
            #pragma unroll
            for (int pi = 0; pi < 8; pi++) {
                ull t2 = *reinterpret_cast<const ull*>(&tx_s[i][2 * (pbase + pi)]);
                accA[pi] = fma2(wd0, t2, accA[pi]);
                accB[pi] = fma2(wd1, t2, accB[pi]);
            }
        }
        #pragma unroll
        for (int pi = 0; pi < 8; pi++) {
            int p  = pbase + pi;
            int ra = r0 + 2 * p, rb = ra + 1;
            float x0, x1, y0, y1;
            unpack2(accA[pi], x0, y0);
            unpack2(accB[pi], x1, y1);
            out[(size_t)ra * NOISE + jj]      = x0;
            out[(size_t)ra * NOISE + jj + 64] = x1;
            out[(size_t)rb * NOISE + jj]      = y0;
            out[(size_t)rb * NOISE + jj + 64] = y1;
        }
    }
}

// ============================================================================
extern "C" void kernel_launch(void* const* d_in, const int* in_sizes, int n_in,
                              void* d_out, int out_size) {
    (void)in_sizes; (void)n_in; (void)out_size;
    const int*   gid   = (const int*)  d_in[0];   // batched_graphs [B]
    const float* chain = (const float*)d_in[1];   // batched_chain  [B]
    const float* td    = (const float*)d_in[2];   // trigger_data   [B,64]
    const float* tx    = (const float*)d_in[3];   // tx_start_time  [B,8]
    const int*   edges = (const int*)  d_in[4];   // edges [64,2,16384]
    const float* gw    = (const float*)d_in[5];   // gcn_w scalar
    const float* gb    = (const float*)d_in[6];   // gcn_b scalar
    const float* trigW = (const float*)d_in[7];   // [64,32]
    const float* trigb = (const float*)d_in[8];   // [32]
    const float* embW  = (const float*)d_in[9];   // [2089,128]
    const float* embb  = (const float*)d_in[10];  // [128]
    float* out = (float*)d_out;                   // [B,128]

    gcn_precompute<<<NGRAPH, 512>>>(edges, gw, gb, embW, embb);
    noise_main<<<B_TOTAL / RROWS, 128>>>(gid, chain, td, tx, trigW, trigb, embW, out);
}